// round 11
// baseline (speedup 1.0000x reference)
#include <cuda_runtime.h>
#include <cstdint>

#define RES 256
#define N_TOTAL (8 * 65536)
#define THREADS 256
#define NBLK (N_TOTAL / THREADS / 2)       // 1024 blocks, 2 pts/thread

__device__ __forceinline__ uint64_t evict_last_policy() {
    uint64_t pol;
    asm("createpolicy.fractional.L2::evict_last.b64 %0, 1.0;" : "=l"(pol));
    return pol;
}

__device__ __forceinline__ float4 ldg_keep4(const float* p, uint64_t pol) {
    float4 v;
    asm volatile("ld.global.nc.L2::cache_hint.v4.f32 {%0,%1,%2,%3}, [%4], %5;"
                 : "=f"(v.x), "=f"(v.y), "=f"(v.z), "=f"(v.w)
                 : "l"(p), "l"(pol));
    return v;
}

__device__ __forceinline__ float ldg_keep(const float* p, uint64_t pol) {
    float v;
    asm volatile("ld.global.nc.L2::cache_hint.f32 %0, [%1], %2;"
                 : "=f"(v) : "l"(p), "l"(pol));
    return v;
}

__device__ __forceinline__ float sel4(float4 v, int o) {
    float r = (o == 1) ? v.y : v.x;
    r = (o == 2) ? v.z : r;
    r = (o == 3) ? v.w : r;
    return r;
}

__global__ __launch_bounds__(THREADS) void volume_sample_kernel(
    const float* __restrict__ x,
    const float* __restrict__ vol,
    float* __restrict__ out)
{
    int t = blockIdx.x * THREADS + threadIdx.x;     // 0..262143

    uint64_t pol = evict_last_policy();

    // coords for points 2t, 2t+1: 6 floats, 8B-aligned. Plain __ldg -> L2-retained.
    const float2* cp = (const float2*)x + (size_t)t * 3;
    float2 c0 = __ldg(cp);
    float2 c1 = __ldg(cp + 1);
    float2 c2 = __ldg(cp + 2);

    float gxa[2] = { c0.x, c1.y };
    float gya[2] = { c0.y, c2.x };
    float gza[2] = { c1.x, c2.y };

    float tx[2], ty[2], tz[2];
    int   row[2][4];
    int   basei[2], ao[2], bo[2], cx1a[2];
    bool  ex[2];
    bool  m_a[2][4], m_b[2][4];   // validity masks for a (x0) / b (x1) per row

    #pragma unroll
    for (int k = 0; k < 2; k++) {
        // EXTENT=0.5 fold: ix = 256*gx + 127.5
        float ix = fmaf(gxa[k], 256.0f, 127.5f);
        float iy = fmaf(gya[k], 256.0f, 127.5f);
        float iz = fmaf(gza[k], 256.0f, 127.5f);

        float fx0 = floorf(ix), fy0 = floorf(iy), fz0 = floorf(iz);
        tx[k] = ix - fx0;  ty[k] = iy - fy0;  tz[k] = iz - fz0;

        int x0 = (int)fx0, y0 = (int)fy0, z0 = (int)fz0;
        int x1 = x0 + 1,   y1 = y0 + 1,   z1 = z0 + 1;

        bool vx0 = (x0 >= 0) & (x0 < RES);
        bool vx1 = (x1 >= 0) & (x1 < RES);
        bool vy0 = (y0 >= 0) & (y0 < RES);
        bool vy1 = (y1 >= 0) & (y1 < RES);
        bool vz0 = (z0 >= 0) & (z0 < RES);
        bool vz1 = (z1 >= 0) & (z1 < RES);

        int cx0 = min(max(x0, 0), RES - 1);
        int cx1 = min(max(x1, 0), RES - 1);
        int cy0 = min(max(y0, 0), RES - 1);
        int cy1 = min(max(y1, 0), RES - 1);
        int cz0 = min(max(z0, 0), RES - 1);
        int cz1 = min(max(z1, 0), RES - 1);

        int pz0 = cz0 << 16;          // * RES*RES (fits int32: < 2^24)
        int pz1 = cz1 << 16;
        row[k][0] = pz0 + (cy0 << 8); // (z0,y0)
        row[k][1] = pz0 + (cy1 << 8); // (z0,y1)
        row[k][2] = pz1 + (cy0 << 8); // (z1,y0)
        row[k][3] = pz1 + (cy1 << 8); // (z1,y1)

        basei[k] = cx0 & ~3;          // 16B aligned, always in-bounds
        ao[k]    = cx0 - basei[k];
        int d1   = cx1 - basei[k];
        bo[k]    = min(d1, 3);
        ex[k]    = (d1 == 4);
        cx1a[k]  = cx1;

        m_a[k][0] = vz0 & vy0 & vx0;  m_b[k][0] = vz0 & vy0 & vx1;
        m_a[k][1] = vz0 & vy1 & vx0;  m_b[k][1] = vz0 & vy1 & vx1;
        m_a[k][2] = vz1 & vy0 & vx0;  m_b[k][2] = vz1 & vy0 & vx1;
        m_a[k][3] = vz1 & vy1 & vx0;  m_b[k][3] = vz1 & vy1 & vx1;
    }

    // ---- batched loads: 8 independent vector gathers in flight ----
    float4 q[2][4];
    #pragma unroll
    for (int k = 0; k < 2; k++)
        #pragma unroll
        for (int r = 0; r < 4; r++)
            q[k][r] = ldg_keep4(vol + row[k][r] + basei[k], pol);

    float e[2][4] = {{0.f,0.f,0.f,0.f},{0.f,0.f,0.f,0.f}};
    #pragma unroll
    for (int k = 0; k < 2; k++)
        if (ex[k])
            #pragma unroll
            for (int r = 0; r < 4; r++)
                e[k][r] = ldg_keep(vol + row[k][r] + cx1a[k], pol);

    // ---- blend + trilinear ----
    float res[2];
    #pragma unroll
    for (int k = 0; k < 2; k++) {
        float a[4], b[4];
        #pragma unroll
        for (int r = 0; r < 4; r++) {
            float av = sel4(q[k][r], ao[k]);
            float bv = ex[k] ? e[k][r] : sel4(q[k][r], bo[k]);
            a[r] = m_a[k][r] ? av : 0.0f;
            b[r] = m_b[k][r] ? bv : 0.0f;
        }
        float c00 = fmaf(tx[k], b[0] - a[0], a[0]);
        float c01 = fmaf(tx[k], b[1] - a[1], a[1]);
        float c10 = fmaf(tx[k], b[2] - a[2], a[2]);
        float c11 = fmaf(tx[k], b[3] - a[3], a[3]);
        float c0  = fmaf(ty[k], c01 - c00, c00);
        float c1  = fmaf(ty[k], c11 - c10, c10);
        res[k] = 100.0f * fmaf(tz[k], c1 - c0, c0);
    }

    // vector streaming store (out + 2t is 8B-aligned)
    asm volatile("st.global.cs.v2.f32 [%0], {%1, %2};"
                 :: "l"(out + 2 * (size_t)t), "f"(res[0]), "f"(res[1]) : "memory");
}

extern "C" void kernel_launch(void* const* d_in, const int* in_sizes, int n_in,
                              void* d_out, int out_size)
{
    const float* x   = (const float*)d_in[0];  // [8, 65536, 3] f32
    const float* vol = (const float*)d_in[1];  // [256,256,256] f32
    float* out = (float*)d_out;                // [8, 65536] f32

    volume_sample_kernel<<<NBLK, THREADS>>>(x, vol, out);
}